// round 5
// baseline (speedup 1.0000x reference)
#include <cuda_runtime.h>
#include <cuda_bf16.h>

// Problem constants (fixed shapes)
constexpr int QN = 16;      // query rows
constexpr int D  = 384;     // embedding dim
constexpr int NV = D / 4;   // float4 per row
constexpr int N  = 50000;   // corpus docs
constexpr int TOTAL = QN * N;
constexpr int NBIN = 65536; // 16-bit sim-order buckets per row

// PAV decomposition
constexpr int TPR  = 1280;            // PAV threads per row
constexpr int LL   = 40;              // elements per PAV thread (1280*40=51200>=N)
constexpr int TBA  = 128;             // threads per pavA block
constexpr int NBA  = TPR / TBA;       // 10 pavA blocks per row
constexpr int CHUNK = TBA * LL;       // 5120 elements per pavA block (40KB smem)
constexpr int NM   = 40;              // level-1 mergers per row
constexpr int MW   = TPR / NM;        // 32 lists per merger
constexpr int MCAP = MW * LL;         // max blocks per merger output
constexpr int NBC  = 10;              // pavC blocks per row
constexpr int CC   = N / NBC;         // 5000 elements per pavC block

// ---------------- static device scratch (no allocations allowed) ------------
__device__ unsigned long long g_v64[TOTAL];
__device__ unsigned long long g_v64s[TOTAL];
__device__ unsigned g_hist[QN * NBIN];     // bucket counts -> start offsets

__device__ double g_asum[QN * TPR * LL];   // phase-A per-thread lists
__device__ int    g_acnt[QN * TPR * LL];
__device__ int    g_anb[QN * TPR];

__device__ double g_m1s[QN * NM * MCAP];   // level-1 merged lists
__device__ int    g_m1c[QN * NM * MCAP];
__device__ int    g_m1n[QN * NM];

__device__ double g_fs[TOTAL];             // final block means
__device__ int    g_fc[TOTAL];
__device__ int    g_fe[TOTAL];             // final block end positions
__device__ int    g_B[QN];                 // final block counts

__device__ __forceinline__ unsigned ord_of(unsigned u) {
    return u ^ ((u & 0x80000000u) ? 0xFFFFFFFFu : 0x80000000u);
}

// ---------------- sims + value build + bucket histogram ----------------------
// Persistent blocks: stage+normalize q once, then warps loop over docs.
__global__ __launch_bounds__(256) void sim_kernel(
    const float* __restrict__ qg, const float* __restrict__ cg,
    float* __restrict__ sims, unsigned long long* __restrict__ vals,
    unsigned* __restrict__ hist)
{
    __shared__ float4 qsh[QN * NV];   // 24 KB
    __shared__ float qinv[QN];
    int tid = threadIdx.x;

    for (int i = tid; i < QN * NV; i += 256)
        qsh[i] = reinterpret_cast<const float4*>(qg)[i];
    __syncthreads();
    if (tid < QN) {
        float ss = 0.f;
        const float4* row = qsh + tid * NV;
        #pragma unroll 8
        for (int j = 0; j < NV; j++) {
            float4 v = row[j];
            ss += v.x*v.x + v.y*v.y + v.z*v.z + v.w*v.w;
        }
        qinv[tid] = 1.0f / fmaxf(sqrtf(ss), 1e-12f);
    }
    __syncthreads();
    for (int i = tid; i < QN * NV; i += 256) {
        float s = qinv[i / NV];
        float4 v = qsh[i];
        v.x *= s; v.y *= s; v.z *= s; v.w *= s;
        qsh[i] = v;
    }
    __syncthreads();

    const int warp = tid >> 5, lane = tid & 31;
    const int gw = blockIdx.x * 8 + warp;
    const int NW = gridDim.x * 8;

    for (int doc = gw; doc < N; doc += NW) {
        const float4* cp = reinterpret_cast<const float4*>(cg + (size_t)doc * D);
        float4 cv[3];
        #pragma unroll
        for (int j = 0; j < 3; j++) cv[j] = cp[lane + 32 * j];

        float ss = 0.f;
        #pragma unroll
        for (int j = 0; j < 3; j++)
            ss += cv[j].x*cv[j].x + cv[j].y*cv[j].y + cv[j].z*cv[j].z + cv[j].w*cv[j].w;

        float acc[QN];
        #pragma unroll
        for (int r = 0; r < QN; r++) {
            float a = 0.f;
            #pragma unroll
            for (int j = 0; j < 3; j++) {
                float4 qv = qsh[r * NV + lane + 32 * j];
                a += qv.x*cv[j].x + qv.y*cv[j].y + qv.z*cv[j].z + qv.w*cv[j].w;
            }
            acc[r] = a;
        }
        #pragma unroll
        for (int o = 16; o; o >>= 1) {
            ss += __shfl_xor_sync(0xFFFFFFFFu, ss, o);
            #pragma unroll
            for (int r = 0; r < QN; r++)
                acc[r] += __shfl_xor_sync(0xFFFFFFFFu, acc[r], o);
        }
        if (lane == 0) {
            float cinv = 1.0f / fmaxf(sqrtf(ss), 1e-12f);
            #pragma unroll
            for (int r = 0; r < QN; r++) {
                float sim = acc[r] * cinv;
                int gi = r * N + doc;
                sims[gi] = sim;
                unsigned u = __float_as_uint(sim);
                vals[gi] = ((unsigned long long)u << 32) | (unsigned long long)gi;
                atomicAdd(&hist[(r << 16) | (ord_of(u) >> 16)], 1u);
            }
        }
    }
}

// ---------------- per-row exclusive scan of bucket counts --------------------
// 16 blocks (one per row) x 512 threads, 128 bins/thread, two-pass over hist.
__global__ __launch_bounds__(512) void scan_kernel(unsigned* __restrict__ hist)
{
    const int row = blockIdx.x;
    const int t = threadIdx.x;
    const int base = row * NBIN + t * 128;

    unsigned sum = 0;
    for (int j = 0; j < 128; j++) sum += hist[base + j];

    __shared__ unsigned s[512];
    s[t] = sum;
    __syncthreads();
    // Hillis-Steele inclusive scan over 512 thread sums
    #pragma unroll
    for (int off = 1; off < 512; off <<= 1) {
        unsigned v = (t >= off) ? s[t - off] : 0u;
        __syncthreads();
        s[t] += v;
        __syncthreads();
    }
    unsigned excl = s[t] - sum + (unsigned)(row * N);
    for (int j = 0; j < 128; j++) {
        unsigned c = hist[base + j];
        hist[base + j] = excl;
        excl += c;
    }
}

// ---------------- scatter into bucket-sorted order ---------------------------
__global__ __launch_bounds__(256) void scatter_kernel(
    const unsigned long long* __restrict__ vals,
    unsigned long long* __restrict__ sorted, unsigned* __restrict__ hist)
{
    int gi = blockIdx.x * 256 + threadIdx.x;
    if (gi >= TOTAL) return;
    unsigned long long v = vals[gi];
    int row = gi / N;
    unsigned u = (unsigned)(v >> 32);
    unsigned bin = (row << 16) | (ord_of(u) >> 16);
    unsigned pos = atomicAdd(&hist[bin], 1u);
    sorted[pos] = v;
}

// ---------------- PAV phase A: chunk-local PAV (160 blocks) ------------------
// Sorted vals carry [sim bits:32][gidx:20]; ascending sim == descending z
// (z = -10*sim). y_i = z_i - (N - i). Pooling violators in any order is
// confluent, so chunk-local PAV followed by list merges is exact.
__global__ __launch_bounds__(TBA) void pavA_kernel(
    const unsigned long long* __restrict__ vals)
{
    __shared__ unsigned long long sh[CHUNK];   // 40 KB
    const int row = blockIdx.y;
    const int bi  = blockIdx.x;
    const int t   = threadIdx.x;
    const int blo = bi * CHUNK;
    const int cnt = min(CHUNK, N - blo);

    for (int i = t; i < cnt; i += TBA)
        sh[i] = vals[row * N + blo + i];
    __syncthreads();

    const int lo = t * LL;
    const int hi = min(cnt, lo + LL);

    double ls[LL];
    int    lc[LL];
    int nb = 0;
    for (int i = lo; i < hi; i++) {
        unsigned long long v = sh[i];
        float sim = __uint_as_float((unsigned)(v >> 32));
        int gpos = blo + i;
        double cs = (double)(sim * -10.0f) - (double)(N - gpos);
        int cc = 1;
        while (nb > 0 && ls[nb - 1] * (double)cc < cs * (double)lc[nb - 1]) {
            cs += ls[nb - 1]; cc += lc[nb - 1]; nb--;
        }
        ls[nb] = cs; lc[nb] = cc; nb++;
    }
    const int gt = bi * TBA + t;
    const int ob = (row * TPR + gt) * LL;
    for (int b = 0; b < nb; b++) {
        g_asum[ob + b] = ls[b];
        g_acnt[ob + b] = lc[b];
    }
    g_anb[row * TPR + gt] = nb;
}

// ---------------- PAV phase B: 2-level list merge ----------------------------
__global__ __launch_bounds__(64) void pavB_kernel()
{
    const int row = blockIdx.x;
    const int t = threadIdx.x;

    if (t < NM) {
        const int ob = (row * NM + t) * MCAP;
        int B = 0;
        for (int tt = t * MW; tt < t * MW + MW; tt++) {
            int nbt = g_anb[row * TPR + tt];
            const int bb = (row * TPR + tt) * LL;
            for (int b = 0; b < nbt; b++) {
                double cs = g_asum[bb + b];
                int cc = g_acnt[bb + b];
                while (B > 0 && g_m1s[ob + B - 1] * (double)cc < cs * (double)g_m1c[ob + B - 1]) {
                    cs += g_m1s[ob + B - 1]; cc += g_m1c[ob + B - 1]; B--;
                }
                g_m1s[ob + B] = cs; g_m1c[ob + B] = cc; B++;
            }
        }
        g_m1n[row * NM + t] = B;
    }
    __syncthreads();

    if (t == 0) {
        const int fb = row * N;
        int B = 0;
        for (int m = 0; m < NM; m++) {
            int nm = g_m1n[row * NM + m];
            const int ob = (row * NM + m) * MCAP;
            for (int b = 0; b < nm; b++) {
                double cs = g_m1s[ob + b];
                int cc = g_m1c[ob + b];
                while (B > 0 && g_fs[fb + B - 1] * (double)cc < cs * (double)g_fc[fb + B - 1]) {
                    cs += g_fs[fb + B - 1]; cc += g_fc[fb + B - 1]; B--;
                }
                g_fs[fb + B] = cs; g_fc[fb + B] = cc; B++;
            }
        }
        int e = 0;
        for (int b = 0; b < B; b++) {
            e += g_fc[fb + b];
            g_fe[fb + b] = e;
            g_fs[fb + b] = g_fs[fb + b] / (double)g_fc[fb + b];  // -> mean
        }
        g_B[row] = B;
    }
}

// ---------------- PAV phase C: expand + scatter ------------------------------
__global__ __launch_bounds__(256) void pavC_kernel(
    const unsigned long long* __restrict__ vals, float* __restrict__ ranks)
{
    const int row = blockIdx.y;
    const int bi  = blockIdx.x;
    const int t   = threadIdx.x;
    const int blo = bi * CC;
    const int B   = g_B[row];
    const int fb  = row * N;

    for (int i = blo + t; i < blo + CC; i += 256) {
        unsigned long long v = vals[row * N + i];
        float sim = __uint_as_float((unsigned)(v >> 32));
        float z = sim * -10.0f;
        int loB = 0, hiB = B;
        while (loB < hiB) {
            int mid = (loB + hiB) >> 1;
            if (g_fe[fb + mid] > i) hiB = mid; else loB = mid + 1;
        }
        double primal = (double)z - g_fs[fb + loB];
        ranks[(unsigned)(v & 0xFFFFFu)] = (float)primal;
    }
}

// ---------------- launch -----------------------------------------------------
extern "C" void kernel_launch(void* const* d_in, const int* in_sizes, int n_in,
                              void* d_out, int out_size)
{
    const float* q = (const float*)d_in[0];
    const float* c = (const float*)d_in[1];
    float* out = (float*)d_out;
    float* sims = out;            // [QN*N]
    float* ranks = out + TOTAL;   // [QN*N]

    void *pv = nullptr, *pvs = nullptr, *ph = nullptr;
    cudaGetSymbolAddress(&pv, g_v64);
    cudaGetSymbolAddress(&pvs, g_v64s);
    cudaGetSymbolAddress(&ph, g_hist);

    cudaMemsetAsync(ph, 0, QN * NBIN * sizeof(unsigned));

    sim_kernel<<<200, 256>>>(q, c, sims, (unsigned long long*)pv,
                             (unsigned*)ph);
    scan_kernel<<<QN, 512>>>((unsigned*)ph);
    scatter_kernel<<<(TOTAL + 255) / 256, 256>>>(
        (const unsigned long long*)pv, (unsigned long long*)pvs,
        (unsigned*)ph);

    dim3 gA(NBA, QN);
    pavA_kernel<<<gA, TBA>>>((const unsigned long long*)pvs);
    pavB_kernel<<<QN, 64>>>();
    dim3 gC(NBC, QN);
    pavC_kernel<<<gC, 256>>>((const unsigned long long*)pvs, ranks);
}